// round 17
// baseline (speedup 1.0000x reference)
#include <cuda_runtime.h>
#include <cstdint>

#define NN 50000      // nodes
#define NE 800000     // edges
#define NP 50048      // nodes padded to multiple of 128
#define NB 98         // scan blocks: ceil(NP/512)
#define ED 64         // edge feature dim
#define HID 152
#define PK2_1 112     // layer-1 K pairs (224 floats, padded; mult of 8)
#define PK2_2 192     // layer-2/3 K pairs (384 floats; mult of 8)

// ---------------- scratch (device globals; no allocation allowed) ----------
__device__ int   g_cnt[NP];
__device__ int   g_fill[NP];
__device__ int   g_base[NP + 1];
__device__ int   g_bsum[128];
__device__ int   g_src[NE];
__device__ int   g_eid[NE];
__device__ float g_eagg[(size_t)NP * ED];
__device__ float g_h1[(size_t)NP * HID];
__device__ float g_h2[(size_t)NP * HID];
// pre-split bf16x2 hi/lo GEMM inputs
__device__ uint32_t g_xh1[(size_t)NP * PK2_1];
__device__ uint32_t g_xl1[(size_t)NP * PK2_1];
__device__ uint32_t g_xh2[(size_t)NP * PK2_2];
__device__ uint32_t g_xl2[(size_t)NP * PK2_2];
// fused weights: float intermediates + split versions
__device__ float    g_wc1[192 * 224];
__device__ float    g_wc2[192 * 384];
__device__ float    g_wc3[64 * 384];
__device__ uint32_t g_wh1[192 * PK2_1], g_wl1[192 * PK2_1];
__device__ uint32_t g_wh2[192 * PK2_2], g_wl2[192 * PK2_2];
__device__ uint32_t g_wh3[64 * PK2_2],  g_wl3[64 * PK2_2];

// ---------------- bf16 hi/lo split helpers ----------------------------------
__device__ __forceinline__ uint32_t pack_bf16x2(float f_even, float f_odd) {
    uint32_t r;
    asm("cvt.rn.satfinite.bf16x2.f32 %0, %1, %2;" : "=r"(r) : "f"(f_odd), "f"(f_even));
    return r;
}
__device__ __forceinline__ void split_pair(float fe, float fo, uint32_t& hi, uint32_t& lo) {
    hi = pack_bf16x2(fe, fo);
    float he = __uint_as_float(hi << 16);
    float ho = __uint_as_float(hi & 0xFFFF0000u);
    lo = pack_bf16x2(fe - he, fo - ho);
}
__device__ __forceinline__ void store_split4(uint32_t* XH, uint32_t* XL, size_t idx, float4 v) {
    uint32_t h0, l0, h1, l1;
    split_pair(v.x, v.y, h0, l0);
    split_pair(v.z, v.w, h1, l1);
    *(uint2*)(XH + idx) = make_uint2(h0, h1);
    *(uint2*)(XL + idx) = make_uint2(l0, l1);
}

// ---------------- utility ---------------------------------------------------
__global__ void k_zero_f(float* __restrict__ p, int n) {
    int t = blockIdx.x * blockDim.x + threadIdx.x;
    if (t < n) p[t] = 0.f;
}
__global__ void k_zero_i(int* __restrict__ p, int n) {
    int t = blockIdx.x * blockDim.x + threadIdx.x;
    if (t < n) p[t] = 0;
}

// ---------------- CSR build -------------------------------------------------
__global__ void k_count(const int* __restrict__ dst) {
    int t = blockIdx.x * blockDim.x + threadIdx.x;
    if (t < NE) atomicAdd(&g_cnt[dst[t]], 1);
}
__global__ void k_scan1() {
    __shared__ int sh[512];
    int b = blockIdx.x, t = threadIdx.x, i = b * 512 + t;
    int v = (i < NP) ? g_cnt[i] : 0;
    sh[t] = v;
    __syncthreads();
#pragma unroll
    for (int o = 1; o < 512; o <<= 1) {
        int x = (t >= o) ? sh[t - o] : 0;
        __syncthreads();
        sh[t] += x;
        __syncthreads();
    }
    if (i < NP) g_base[i + 1] = sh[t];
    if (t == 511) g_bsum[b] = sh[511];
}
__global__ void k_scan2() {
    if (threadIdx.x == 0) {
        int s = 0;
        for (int b = 0; b < NB; b++) { int c = g_bsum[b]; g_bsum[b] = s; s += c; }
    }
}
__global__ void k_scan3() {
    int i = blockIdx.x * blockDim.x + threadIdx.x;
    if (i < NP) g_base[i + 1] += g_bsum[i >> 9];
    if (i == 0) g_base[0] = 0;
}
__global__ void k_fill(const int* __restrict__ src, const int* __restrict__ dst) {
    int t = blockIdx.x * blockDim.x + threadIdx.x;
    if (t >= NE) return;
    int d = dst[t];
    int p = g_base[d] + atomicAdd(&g_fill[d], 1);
    g_src[p] = src[t];
    g_eid[p] = t;
}

// ---------------- edge-feature gather-sum per dst node ----------------------
__global__ void k_gather_e(const float* __restrict__ ef) {
    int w = (blockIdx.x * blockDim.x + threadIdx.x) >> 5;
    int lane = threadIdx.x & 31;
    if (w >= NN || lane >= 16) return;
    int e0 = g_base[w], e1 = g_base[w + 1];
    float4 a = {0.f, 0.f, 0.f, 0.f};
    for (int e = e0; e < e1; e++) {
        int id = g_eid[e];
        float4 v = *(const float4*)(ef + (size_t)id * ED + lane * 4);
        a.x += v.x; a.y += v.y; a.z += v.z; a.w += v.w;
    }
    *(float4*)(g_eagg + (size_t)w * ED + lane * 4) = a;
}

// ---------------- static pair columns (split, once per launch) ---------------
// pairs per row v: [0,FP2)=x | [FP2,2FP2)=mean | [2FP2,2FP2+32)=inv*eagg
//                  pair 2FP2+32 = (indicator,0) | rest zero ; pad rows all zero
template <int PK2, int FP2>
__global__ void k_static_s(uint32_t* __restrict__ XH, uint32_t* __restrict__ XL) {
    int t = blockIdx.x * blockDim.x + threadIdx.x;
    if (t >= NP * PK2) return;
    int v = t / PK2, p = t - v * PK2;
    if (v >= NN) { XH[t] = 0u; XL[t] = 0u; return; }
    if (p < 2 * FP2) return;                  // dynamic, written per layer
    int dg = g_cnt[v];
    float f0 = 0.f, f1 = 0.f;
    if (p < 2 * FP2 + 32) {
        float inv = 1.f / (float)max(dg, 1);
        int c = (p - 2 * FP2) * 2;
        f0 = inv * g_eagg[(size_t)v * ED + c];
        f1 = inv * g_eagg[(size_t)v * ED + c + 1];
    } else if (p == 2 * FP2 + 32) {
        f0 = (dg > 0) ? 1.f : 0.f;
    }
    uint32_t h, l;
    split_pair(f0, f1, h, l);
    XH[t] = h; XL[t] = l;
}

// ---------------- per-layer gather: self + mean, written split --------------
template <int NC4, int PK2>
__global__ void k_gather_s(const float* __restrict__ X, int ldx,
                           uint32_t* __restrict__ XH, uint32_t* __restrict__ XL) {
    int w = (blockIdx.x * blockDim.x + threadIdx.x) >> 5;
    int lane = threadIdx.x & 31;
    if (w >= NN) return;
    int e0 = g_base[w], e1 = g_base[w + 1];
    int c0 = lane, c1 = lane + 32;
    float4 a0 = {0.f, 0.f, 0.f, 0.f};
    float4 a1 = {0.f, 0.f, 0.f, 0.f};
    for (int e = e0; e < e1; e++) {
        int s = g_src[e];
        const float4* row = (const float4*)(X + (size_t)s * ldx);
        if (c0 < NC4) {
            float4 v = row[c0];
            a0.x += v.x; a0.y += v.y; a0.z += v.z; a0.w += v.w;
        }
        if (NC4 > 32 && c1 < NC4) {
            float4 v = row[c1];
            a1.x += v.x; a1.y += v.y; a1.z += v.z; a1.w += v.w;
        }
    }
    float inv = 1.f / fmaxf((float)(e1 - e0), 1.f);
    const float4* xrow = (const float4*)(X + (size_t)w * ldx);
    size_t rb = (size_t)w * PK2;
    if (c0 < NC4) {
        store_split4(XH, XL, rb + 2 * c0, xrow[c0]);
        float4 r; r.x = a0.x * inv; r.y = a0.y * inv; r.z = a0.z * inv; r.w = a0.w * inv;
        store_split4(XH, XL, rb + 2 * NC4 + 2 * c0, r);
    }
    if (NC4 > 32 && c1 < NC4) {
        store_split4(XH, XL, rb + 2 * c1, xrow[c1]);
        float4 r; r.x = a1.x * inv; r.y = a1.y * inv; r.z = a1.z * inv; r.w = a1.w * inv;
        store_split4(XH, XL, rb + 2 * NC4 + 2 * c1, r);
    }
}

// ---------------- build fused weight Wc (float intermediate) ----------------
__global__ void k_wc(const float* __restrict__ Wm, const float* __restrict__ bm,
                     const float* __restrict__ Wa, float* __restrict__ Wc,
                     int Fin, int Fm, int Fout, int Kp) {
    int col = blockIdx.x * blockDim.x + threadIdx.x;
    int j = blockIdx.y;
    int K1 = 2 * Fin + ED + 1;
    if (col >= K1 || j >= Fout) return;
    int WmK = Fin + ED;
    int WaK = Fin + Fm;
    const float* wah = Wa + (size_t)j * WaK + Fin;
    float val;
    if (col < Fin) {
        val = Wa[(size_t)j * WaK + col];
    } else if (col < 2 * Fin) {
        int i = col - Fin;
        float s = 0.f;
        for (int t = 0; t < Fm; t++) s += wah[t] * Wm[(size_t)t * WmK + i];
        val = s;
    } else if (col < 2 * Fin + ED) {
        int i = col - 2 * Fin;
        float s = 0.f;
        for (int t = 0; t < Fm; t++) s += wah[t] * Wm[(size_t)t * WmK + Fin + i];
        val = s;
    } else {
        float s = 0.f;
        for (int t = 0; t < Fm; t++) s += wah[t] * bm[t];
        val = s;
    }
    Wc[(size_t)j * Kp + col] = val;
}

// ---------------- split float weight rows -> hi/lo bf16x2 pairs --------------
__global__ void k_split(const float* __restrict__ W, uint32_t* __restrict__ WH,
                        uint32_t* __restrict__ WL, int rows, int kp_f, int pk2) {
    int t = blockIdx.x * blockDim.x + threadIdx.x;
    if (t >= rows * pk2) return;
    int r = t / pk2, p = t - r * pk2;
    float f0 = (2 * p     < kp_f) ? W[(size_t)r * kp_f + 2 * p]     : 0.f;
    float f1 = (2 * p + 1 < kp_f) ? W[(size_t)r * kp_f + 2 * p + 1] : 0.f;
    uint32_t h, l;
    split_pair(f0, f1, h, l);
    WH[t] = h; WL[t] = l;
}

// ---------------- GEMM: pre-split bf16x3 + ldmatrix + double buffer ---------
// C = relu(A @ B^T + bias). BM=128, BN=64, BK=16 (8 pairs/iter); 256 threads,
// 8 warps 4(m)x2(n), warp tile 32x32. Inner loop: 8 LDSM + 24 MMA + copies.
__device__ __forceinline__ uint32_t smem_u32(const void* p) {
    return (uint32_t)__cvta_generic_to_shared(p);
}
__device__ __forceinline__ void ldsm_x4(uint32_t& r0, uint32_t& r1, uint32_t& r2,
                                        uint32_t& r3, uint32_t addr) {
    asm volatile("ldmatrix.sync.aligned.m8n8.x4.shared.b16 {%0,%1,%2,%3}, [%4];"
                 : "=r"(r0), "=r"(r1), "=r"(r2), "=r"(r3) : "r"(addr));
}
__device__ __forceinline__ void mma_bf16(float* c, const uint32_t* a, const uint32_t* b) {
    asm volatile(
        "mma.sync.aligned.m16n8k16.row.col.f32.bf16.bf16.f32 "
        "{%0,%1,%2,%3}, {%4,%5,%6,%7}, {%8,%9}, {%0,%1,%2,%3};"
        : "+f"(c[0]), "+f"(c[1]), "+f"(c[2]), "+f"(c[3])
        : "r"(a[0]), "r"(a[1]), "r"(a[2]), "r"(a[3]), "r"(b[0]), "r"(b[1]));
}

__global__ __launch_bounds__(256) void k_gemm_p(
    const uint32_t* __restrict__ AH, const uint32_t* __restrict__ AL,
    const uint32_t* __restrict__ BH, const uint32_t* __restrict__ BL,
    const float* __restrict__ bias, float* __restrict__ C,
    int M, int Nout, int PK2, int ldc) {
    // pitch 12 words: LDSM phase banks 12i mod 32 all-distinct -> conflict-free
    __shared__ uint32_t sAh[2][128][12], sAl[2][128][12];
    __shared__ uint32_t sBh[2][64][12],  sBl[2][64][12];
    const int m0 = blockIdx.x * 128;
    const int n0 = blockIdx.y * 64;
    const int tid = threadIdx.x;
    const int lane = tid & 31, wid = tid >> 5;
    const int mw = wid >> 1, nw = wid & 1;     // 4 x 2 warp grid
    const int g = lane >> 2, t4 = lane & 3;

    // staging map: A 1024 words -> uint4/thread; B 512 words -> uint2/thread
    const int ar = tid >> 1, ac = (tid & 1) << 2;
    const int br = tid >> 2, bc = (tid & 3) << 1;
    // ldmatrix lane addressing
    const int arow = mw * 32 + (lane & 15);
    const int asel = (lane >> 4) << 2;
    const int brow = nw * 32 + lane;

    float acc[2][4][4];
#pragma unroll
    for (int i = 0; i < 2; i++)
#pragma unroll
        for (int j = 0; j < 4; j++)
#pragma unroll
            for (int e = 0; e < 4; e++) acc[i][j][e] = 0.f;

    uint4 vah, val_;
    uint2 vbh, vbl;
    auto load_tiles = [&](int kp0) {
        vah  = *(const uint4*)(AH + (size_t)(m0 + ar) * PK2 + kp0 + ac);
        val_ = *(const uint4*)(AL + (size_t)(m0 + ar) * PK2 + kp0 + ac);
        vbh  = *(const uint2*)(BH + (size_t)(n0 + br) * PK2 + kp0 + bc);
        vbl  = *(const uint2*)(BL + (size_t)(n0 + br) * PK2 + kp0 + bc);
    };
    auto store_tiles = [&](int b) {
        *(uint4*)&sAh[b][ar][ac] = vah;
        *(uint4*)&sAl[b][ar][ac] = val_;
        *(uint2*)&sBh[b][br][bc] = vbh;
        *(uint2*)&sBl[b][br][bc] = vbl;
    };
    auto compute = [&](int b) {
        uint32_t ah[2][4], al[2][4], bh[2][4], bl[2][4];
        ldsm_x4(ah[0][0], ah[0][1], ah[0][2], ah[0][3], smem_u32(&sAh[b][arow][asel]));
        ldsm_x4(ah[1][0], ah[1][1], ah[1][2], ah[1][3], smem_u32(&sAh[b][arow + 16][asel]));
        ldsm_x4(al[0][0], al[0][1], al[0][2], al[0][3], smem_u32(&sAl[b][arow][asel]));
        ldsm_x4(al[1][0], al[1][1], al[1][2], al[1][3], smem_u32(&sAl[b][arow + 16][asel]));
        ldsm_x4(bh[0][0], bh[0][1], bh[0][2], bh[0][3], smem_u32(&sBh[b][brow][0]));
        ldsm_x4(bh[1][0], bh[1][1], bh[1][2], bh[1][3], smem_u32(&sBh[b][brow][4]));
        ldsm_x4(bl[0][0], bl[0][1], bl[0][2], bl[0][3], smem_u32(&sBl[b][brow][0]));
        ldsm_x4(bl[1][0], bl[1][1], bl[1][2], bl[1][3], smem_u32(&sBl[b][brow][4]));
#pragma unroll
        for (int i = 0; i < 2; i++)
#pragma unroll
            for (int j = 0; j < 4; j++) {
                uint32_t bbh[2] = {bh[0][j], bh[1][j]};
                uint32_t bbl[2] = {bl[0][j], bl[1][j]};
                mma_bf16(acc[i][j], ah[i], bbh);
                mma_bf16(acc[i][j], al[i], bbh);
                mma_bf16(acc[i][j], ah[i], bbl);
            }
    };

    load_tiles(0);
    store_tiles(0);
    __syncthreads();

    int buf = 0;
    for (int kp0 = 8; kp0 < PK2; kp0 += 8) {
        load_tiles(kp0);       // next tile's GLDs in flight
        compute(buf);
        store_tiles(buf ^ 1);
        __syncthreads();
        buf ^= 1;
    }
    compute(buf);

    // epilogue: bias + relu
#pragma unroll
    for (int i = 0; i < 2; i++) {
#pragma unroll
        for (int j = 0; j < 4; j++) {
            int ncol = n0 + nw * 32 + j * 8 + 2 * t4;
            if (ncol >= Nout) continue;            // Nout multiple of 8: pair safe
            float b0 = bias[ncol], b1 = bias[ncol + 1];
            int mrow = m0 + mw * 32 + i * 16 + g;
            if (mrow < M) {
                float2 r0 = {fmaxf(acc[i][j][0] + b0, 0.f), fmaxf(acc[i][j][1] + b1, 0.f)};
                *(float2*)(C + (size_t)mrow * ldc + ncol) = r0;
            }
            if (mrow + 8 < M) {
                float2 r1 = {fmaxf(acc[i][j][2] + b0, 0.f), fmaxf(acc[i][j][3] + b1, 0.f)};
                *(float2*)(C + (size_t)(mrow + 8) * ldc + ncol) = r1;
            }
        }
    }
}

// ---------------- driver ----------------------------------------------------
extern "C" void kernel_launch(void* const* d_in, const int* in_sizes, int n_in,
                              void* d_out, int out_size) {
    const float* nf  = (const float*)d_in[0];
    const float* ef  = (const float*)d_in[1];
    const float* Wm1 = (const float*)d_in[2];  const float* bm1 = (const float*)d_in[3];
    const float* Wa1 = (const float*)d_in[4];  const float* ba1 = (const float*)d_in[5];
    const float* Wm2 = (const float*)d_in[6];  const float* bm2 = (const float*)d_in[7];
    const float* Wa2 = (const float*)d_in[8];  const float* ba2 = (const float*)d_in[9];
    const float* Wm3 = (const float*)d_in[10]; const float* bm3 = (const float*)d_in[11];
    const float* Wa3 = (const float*)d_in[12]; const float* ba3 = (const float*)d_in[13];
    const int* src = (const int*)d_in[14];
    const int* dst = (const int*)d_in[15];
    float* out = (float*)d_out;

    float *p_h1, *p_h2, *p_wc1, *p_wc2, *p_wc3;
    int *p_cnt, *p_fill;
    uint32_t *p_xh1, *p_xl1, *p_xh2, *p_xl2;
    uint32_t *p_wh1, *p_wl1, *p_wh2, *p_wl2, *p_wh3, *p_wl3;
    cudaGetSymbolAddress((void**)&p_cnt,  g_cnt);
    cudaGetSymbolAddress((void**)&p_fill, g_fill);
    cudaGetSymbolAddress((void**)&p_h1,   g_h1);
    cudaGetSymbolAddress((void**)&p_h2,   g_h2);
    cudaGetSymbolAddress((void**)&p_wc1,  g_wc1);
    cudaGetSymbolAddress((void**)&p_wc2,  g_wc2);
    cudaGetSymbolAddress((void**)&p_wc3,  g_wc3);
    cudaGetSymbolAddress((void**)&p_xh1,  g_xh1);
    cudaGetSymbolAddress((void**)&p_xl1,  g_xl1);
    cudaGetSymbolAddress((void**)&p_xh2,  g_xh2);
    cudaGetSymbolAddress((void**)&p_xl2,  g_xl2);
    cudaGetSymbolAddress((void**)&p_wh1,  g_wh1);
    cudaGetSymbolAddress((void**)&p_wl1,  g_wl1);
    cudaGetSymbolAddress((void**)&p_wh2,  g_wh2);
    cudaGetSymbolAddress((void**)&p_wl2,  g_wl2);
    cudaGetSymbolAddress((void**)&p_wh3,  g_wh3);
    cudaGetSymbolAddress((void**)&p_wl3,  g_wl3);

    const int GW = (NN * 32 + 255) / 256;   // warp-per-node grids

    // ---- CSR build ----
    k_zero_i<<<(NP + 255) / 256, 256>>>(p_cnt, NP);
    k_zero_i<<<(NP + 255) / 256, 256>>>(p_fill, NP);
    k_count<<<(NE + 255) / 256, 256>>>(dst);
    k_scan1<<<NB, 512>>>();
    k_scan2<<<1, 32>>>();
    k_scan3<<<(NP + 255) / 256, 256>>>();
    k_fill<<<(NE + 255) / 256, 256>>>(src, dst);

    // ---- graph-constant: edge agg + static split columns ----
    k_gather_e<<<GW, 256>>>(ef);
    k_static_s<PK2_1, 32><<<(NP * PK2_1 + 255) / 256, 256>>>(p_xh1, p_xl1);
    k_static_s<PK2_2, 76><<<(NP * PK2_2 + 255) / 256, 256>>>(p_xh2, p_xl2);

    // ---- fused weights (float) then split ----
    k_zero_f<<<(192 * 224 + 255) / 256, 256>>>(p_wc1, 192 * 224);
    k_zero_f<<<(192 * 384 + 255) / 256, 256>>>(p_wc2, 192 * 384);
    k_zero_f<<<(64 * 384 + 255) / 256, 256>>>(p_wc3, 64 * 384);
    k_wc<<<dim3(2, 152), 128>>>(Wm1, bm1, Wa1, p_wc1, 64, 152, 152, 224);
    k_wc<<<dim3(3, 152), 128>>>(Wm2, bm2, Wa2, p_wc2, 152, 152, 152, 384);
    k_wc<<<dim3(3, 64), 128>>>(Wm3, bm3, Wa3, p_wc3, 152, 64, 64, 384);
    k_split<<<(192 * PK2_1 + 255) / 256, 256>>>(p_wc1, p_wh1, p_wl1, 192, 224, PK2_1);
    k_split<<<(192 * PK2_2 + 255) / 256, 256>>>(p_wc2, p_wh2, p_wl2, 192, 384, PK2_2);
    k_split<<<(64 * PK2_2 + 255) / 256, 256>>>(p_wc3, p_wh3, p_wl3, 64, 384, PK2_2);

    // ---- layer 1 (64 -> 152) ----
    k_gather_s<16, PK2_1><<<GW, 256>>>(nf, 64, p_xh1, p_xl1);
    k_gemm_p<<<dim3(NP / 128, 3), 256>>>(p_xh1, p_xl1, p_wh1, p_wl1, ba1, p_h1,
                                         NN, 152, PK2_1, HID);

    // ---- layer 2 (152 -> 152) ----
    k_gather_s<38, PK2_2><<<GW, 256>>>(p_h1, HID, p_xh2, p_xl2);
    k_gemm_p<<<dim3(NP / 128, 3), 256>>>(p_xh2, p_xl2, p_wh2, p_wl2, ba2, p_h2,
                                         NN, 152, PK2_2, HID);

    // ---- layer 3 (152 -> 64) ----
    k_gather_s<38, PK2_2><<<GW, 256>>>(p_h2, HID, p_xh2, p_xl2);
    k_gemm_p<<<dim3(NP / 128, 1), 256>>>(p_xh2, p_xl2, p_wh3, p_wl3, ba3, out,
                                         NN, 64, PK2_2, 64);
}